// round 5
// baseline (speedup 1.0000x reference)
#include <cuda_runtime.h>
#include <cuda_bf16.h>
#include <cstdint>
#include <math.h>

// ===========================================================================
// WindowAttentionV2: A-resident split-bf16 mma.sync GEMMs + fp32 attention.
// B=2048 win, N=64 tok, C=256, H=8, D=32.
// ===========================================================================

// ---- device scratch --------------------------------------------------------
__device__ float g_qkv[3u * 2048 * 8 * 2048];          // [(sec*2048+win)*8+h][tok*32+d]
__device__ __nv_bfloat16 g_chi[131072u * 256];
__device__ __nv_bfloat16 g_clo[131072u * 256];
__device__ __nv_bfloat16 g_wqkv_hi[768 * 256];         // [n][k]
__device__ __nv_bfloat16 g_wqkv_lo[768 * 256];
__device__ __nv_bfloat16 g_wproj_hi[256 * 256];
__device__ __nv_bfloat16 g_wproj_lo[256 * 256];
__device__ float g_rel_bias[8 * 64 * 64];
__device__ float g_bias_qkv[768];

// ---- helpers ----------------------------------------------------------------
__device__ __forceinline__ void ffma2(unsigned long long& d,
                                      unsigned long long a,
                                      unsigned long long b) {
    asm("fma.rn.f32x2 %0, %1, %2, %0;" : "+l"(d) : "l"(a), "l"(b));
}
__device__ __forceinline__ float hsum2(unsigned long long v) {
    union { unsigned long long u; float2 f; } c; c.u = v;
    return c.f.x + c.f.y;
}
__device__ __forceinline__ uint32_t smem_u32(const void* p) {
    uint32_t a;
    asm("{ .reg .u64 t; cvta.to.shared.u64 t, %1; cvt.u32.u64 %0, t; }"
        : "=r"(a) : "l"(p));
    return a;
}
__device__ __forceinline__ void mma_bf16(float* c, const uint32_t* a, const uint32_t* b) {
    asm volatile(
        "mma.sync.aligned.m16n8k16.row.col.f32.bf16.bf16.f32 "
        "{%0,%1,%2,%3}, {%4,%5,%6,%7}, {%8,%9}, {%0,%1,%2,%3};"
        : "+f"(c[0]), "+f"(c[1]), "+f"(c[2]), "+f"(c[3])
        : "r"(a[0]), "r"(a[1]), "r"(a[2]), "r"(a[3]), "r"(b[0]), "r"(b[1]));
}
__device__ __forceinline__ void ldm4(uint32_t* r, uint32_t addr) {
    asm volatile("ldmatrix.sync.aligned.m8n8.x4.shared.b16 {%0,%1,%2,%3}, [%4];"
                 : "=r"(r[0]), "=r"(r[1]), "=r"(r[2]), "=r"(r[3]) : "r"(addr));
}
__device__ __forceinline__ void cpasync16(uint32_t dst, const void* src) {
    asm volatile("cp.async.cg.shared.global [%0], [%1], 16;" :: "r"(dst), "l"(src));
}
__device__ __forceinline__ void bf_split(float v, __nv_bfloat16& hi, __nv_bfloat16& lo) {
    hi = __float2bfloat16(v);
    lo = __float2bfloat16(v - __bfloat162float(hi));
}
__device__ __forceinline__ uint32_t pack_bf(__nv_bfloat16 a, __nv_bfloat16 b) {
    return (uint32_t)__bfloat16_as_ushort(a) | ((uint32_t)__bfloat16_as_ushort(b) << 16);
}

// ===========================================================================
// prep_w: weights -> [n][k] bf16 hi/lo, qkv bias pack
// ===========================================================================
__global__ void prep_w_kernel(const float* __restrict__ qkv_w,
                              const float* __restrict__ proj_w,
                              const float* __restrict__ q_bias,
                              const float* __restrict__ v_bias)
{
    int gid = blockIdx.x * blockDim.x + threadIdx.x;
    int gsz = gridDim.x * blockDim.x;
    for (int i = gid; i < 768 * 256; i += gsz) {
        int n = i >> 8, k = i & 255;
        __nv_bfloat16 hi, lo;
        bf_split(qkv_w[(size_t)k * 768 + n], hi, lo);
        g_wqkv_hi[i] = hi; g_wqkv_lo[i] = lo;
    }
    for (int i = gid; i < 256 * 256; i += gsz) {
        int n = i >> 8, k = i & 255;
        __nv_bfloat16 hi, lo;
        bf_split(proj_w[(size_t)k * 256 + n], hi, lo);
        g_wproj_hi[i] = hi; g_wproj_lo[i] = lo;
    }
    for (int i = gid; i < 768; i += gsz)
        g_bias_qkv[i] = (i < 256) ? q_bias[i] : ((i < 512) ? 0.f : v_bias[i - 512]);
}

// ===========================================================================
// cpb: continuous position bias (window-independent)
// ===========================================================================
__global__ void cpb_kernel(const float* __restrict__ coords_table,
                           const float* __restrict__ mlp1_w,
                           const float* __restrict__ mlp1_b,
                           const float* __restrict__ mlp2_w,
                           const int*   __restrict__ rel_pos_index)
{
    __shared__ float bt[225 * 8];
    int t = threadIdx.x;
    if (t < 225) {
        float c0 = coords_table[t * 2 + 0];
        float c1 = coords_table[t * 2 + 1];
        float acc[8];
#pragma unroll
        for (int hh = 0; hh < 8; hh++) acc[hh] = 0.f;
        for (int k = 0; k < 512; k++) {
            float hv = fmaxf(c0 * mlp1_w[k] + c1 * mlp1_w[512 + k] + mlp1_b[k], 0.f);
#pragma unroll
            for (int hh = 0; hh < 8; hh++) acc[hh] += hv * mlp2_w[k * 8 + hh];
        }
#pragma unroll
        for (int hh = 0; hh < 8; hh++) bt[t * 8 + hh] = acc[hh];
    }
    __syncthreads();
    for (int idx = t; idx < 8 * 64 * 64; idx += blockDim.x) {
        int hh = idx >> 12;
        int ij = idx & 4095;
        float v = bt[rel_pos_index[ij] * 8 + hh];
        g_rel_bias[idx] = 16.f / (1.f + __expf(-v));
    }
}

// ===========================================================================
// gemm_ar: A-resident split-bf16 GEMM. CTA owns 128 rows, loops NT ntiles.
// A hi/lo resident in smem (132 KB), B double-buffered k64 chunks (72 KB).
// MODE 0: A = x fp32 (converted in-kernel), B = qkv w, out -> g_qkv (+bias)
// MODE 1: A = g_chi/g_clo,                 B = proj w, out -> Cout  (+bias)
// Block: 256 thr = 8 warps (4m x 2n), warp tile 32x64.
// ===========================================================================
#define LDA 264          // A row stride (bf16): 256 + 8, 528B ≡ 16 mod 128
#define LDB 72           // B row stride (bf16) within k64 chunk

#define A_BYTES   (128 * LDA * 2)        // 67584 per polarity
#define BCH_BYTES (128 * LDB * 2)        // 18432 per polarity
#define BBUF_BYTES (2 * BCH_BYTES)       // hi+lo = 36864
#define SMEM_GEMM (2 * A_BYTES + 2 * BBUF_BYTES)   // 208896

template<int NT, int MODE>
__global__ void __launch_bounds__(256, 1)
gemm_ar_kernel(const float* __restrict__ A_f32,
               const float* __restrict__ bias_ext,
               float* __restrict__ Cout)
{
    extern __shared__ __nv_bfloat16 smb[];
    const uint32_t sb = smem_u32(smb);
    const uint32_t AH = sb;
    const uint32_t AL = AH + A_BYTES;
    const uint32_t BB = AL + A_BYTES;    // two buffers of (hi|lo)

    const int t = threadIdx.x, lane = t & 31, w = t >> 5;
    const int wm = w & 3, wn = w >> 2;
    const int mtile = blockIdx.x;

    const __nv_bfloat16 *gBh, *gBl;
    if (MODE == 0) { gBh = g_wqkv_hi; gBl = g_wqkv_lo; }
    else           { gBh = g_wproj_hi; gBl = g_wproj_lo; }

    // ---- stage B chunk s=0 first (get memory moving) ------------------------
    auto stageB = [&](int s, int buf) {
        const int nt = s >> 2, kc = s & 3;
        const uint32_t dstH = BB + buf * BBUF_BYTES;
        const uint32_t dstL = dstH + BCH_BYTES;
        const size_t gb = (size_t)nt * 128 * 256 + kc * 64;
#pragma unroll
        for (int rep = 0; rep < 4; rep++) {
            int idx = rep * 256 + t;         // 0..1023
            int row = idx >> 3, cg = idx & 7;
            uint32_t so = (uint32_t)(row * LDB + cg * 8) * 2;
            size_t go = gb + (size_t)row * 256 + cg * 8;
            cpasync16(dstH + so, gBh + go);
            cpasync16(dstL + so, gBl + go);
        }
    };

    stageB(0, 0);
    asm volatile("cp.async.commit_group;" ::: "memory");

    // ---- A -> smem hi/lo ------------------------------------------------------
    if (MODE == 0) {
        const float4* src = (const float4*)(A_f32 + (size_t)mtile * 128 * 256);
#pragma unroll
        for (int rep = 0; rep < 32; rep++) {
            int idx = rep * 256 + t;               // 0..8191 float4
            int row = idx >> 6, c4 = idx & 63;
            float4 f = src[idx];
            __nv_bfloat16 h0, h1, h2, h3, l0, l1, l2, l3;
            bf_split(f.x, h0, l0); bf_split(f.y, h1, l1);
            bf_split(f.z, h2, l2); bf_split(f.w, h3, l3);
            uint32_t off = (uint32_t)(row * LDA + c4 * 4) * 2;
            uint2 hv = make_uint2(pack_bf(h0, h1), pack_bf(h2, h3));
            uint2 lv = make_uint2(pack_bf(l0, l1), pack_bf(l2, l3));
            asm volatile("st.shared.v2.b32 [%0], {%1,%2};" :: "r"(AH + off), "r"(hv.x), "r"(hv.y));
            asm volatile("st.shared.v2.b32 [%0], {%1,%2};" :: "r"(AL + off), "r"(lv.x), "r"(lv.y));
        }
    } else {
        const size_t ab = (size_t)mtile * 128 * 256;
#pragma unroll
        for (int rep = 0; rep < 16; rep++) {
            int idx = rep * 256 + t;               // 0..4095 (16B units)
            int row = idx >> 5, cg = idx & 31;
            uint32_t so = (uint32_t)(row * LDA + cg * 8) * 2;
            size_t go = ab + (size_t)row * 256 + cg * 8;
            cpasync16(AH + so, g_chi + go);
            cpasync16(AL + so, g_clo + go);
        }
        asm volatile("cp.async.commit_group;" ::: "memory");
    }

    float acc[2][8][4];
#pragma unroll
    for (int mi = 0; mi < 2; mi++)
#pragma unroll
        for (int n8 = 0; n8 < 8; n8++)
#pragma unroll
            for (int r = 0; r < 4; r++) acc[mi][n8][r] = 0.f;

    const int S = NT * 4;
    for (int s = 0; s < S; s++) {
        __syncthreads();                     // prior readers of buf[(s+1)&1] done
        if (s + 1 < S) {
            stageB(s + 1, (s + 1) & 1);
            asm volatile("cp.async.commit_group;" ::: "memory");
            asm volatile("cp.async.wait_group 1;" ::: "memory");
        } else {
            asm volatile("cp.async.wait_group 0;" ::: "memory");
        }
        __syncthreads();                     // buf[s&1] (and A on first iter) ready

        const uint32_t BH = BB + (s & 1) * BBUF_BYTES;
        const uint32_t BL = BH + BCH_BYTES;
        const int kc = s & 3;

#pragma unroll
        for (int ks = 0; ks < 4; ks++) {
            uint32_t ah[2][4], al[2][4];
            {
                int arow = wm * 32 + (lane & 15);
                int acol = kc * 64 + ks * 16 + ((lane >> 4) << 3);
                uint32_t ao = (uint32_t)(arow * LDA + acol) * 2;
                ldm4(ah[0], AH + ao);
                ldm4(ah[1], AH + ao + 16 * LDA * 2);
                ldm4(al[0], AL + ao);
                ldm4(al[1], AL + ao + 16 * LDA * 2);
            }
            const int quad = lane >> 3, l8 = lane & 7;
            const int bcol = ks * 16 + ((quad & 1) << 3);
#pragma unroll
            for (int np = 0; np < 4; np++) {
                int brow = wn * 64 + np * 16 + ((quad >> 1) << 3) + l8;
                uint32_t bo = (uint32_t)(brow * LDB + bcol) * 2;
                uint32_t bq[4];
                ldm4(bq, BH + bo);
#pragma unroll
                for (int mi = 0; mi < 2; mi++) {
                    mma_bf16(acc[mi][2 * np + 0], ah[mi], bq + 0);  // hi*whi
                    mma_bf16(acc[mi][2 * np + 1], ah[mi], bq + 2);
                    mma_bf16(acc[mi][2 * np + 0], al[mi], bq + 0);  // lo*whi
                    mma_bf16(acc[mi][2 * np + 1], al[mi], bq + 2);
                }
                ldm4(bq, BL + bo);
#pragma unroll
                for (int mi = 0; mi < 2; mi++) {
                    mma_bf16(acc[mi][2 * np + 0], ah[mi], bq + 0);  // hi*wlo
                    mma_bf16(acc[mi][2 * np + 1], ah[mi], bq + 2);
                }
            }
        }

        // ---- epilogue at end of each ntile (registers + gmem only) ----------
        if (kc == 3) {
            const int nt = s >> 2;
            const int row_l = wm * 32 + (lane >> 2);
            const int col_l = wn * 64 + (lane & 3) * 2;
#pragma unroll
            for (int mi = 0; mi < 2; mi++) {
#pragma unroll
                for (int n8 = 0; n8 < 8; n8++) {
                    int gc = nt * 128 + col_l + n8 * 8;
                    if (MODE == 0) {
                        int sec = gc >> 8, hh = (gc >> 5) & 7, d = gc & 31;
                        float b0 = g_bias_qkv[gc], b1 = g_bias_qkv[gc + 1];
#pragma unroll
                        for (int half = 0; half < 2; half++) {
                            int row = mtile * 128 + row_l + mi * 16 + half * 8;
                            int win = row >> 6, tok = row & 63;
                            size_t addr = (((size_t)sec * 2048 + win) * 8 + hh) * 2048
                                          + (size_t)tok * 32 + d;
                            float2 v;
                            v.x = acc[mi][n8][2 * half + 0] + b0;
                            v.y = acc[mi][n8][2 * half + 1] + b1;
                            *(float2*)&g_qkv[addr] = v;
                        }
                    } else {
                        float b0 = bias_ext[gc], b1 = bias_ext[gc + 1];
#pragma unroll
                        for (int half = 0; half < 2; half++) {
                            int row = mtile * 128 + row_l + mi * 16 + half * 8;
                            float2 v;
                            v.x = acc[mi][n8][2 * half + 0] + b0;
                            v.y = acc[mi][n8][2 * half + 1] + b1;
                            *(float2*)&Cout[(size_t)row * 256 + gc] = v;
                        }
                    }
                    acc[mi][n8][0] = acc[mi][n8][1] = acc[mi][n8][2] = acc[mi][n8][3] = 0.f;
                }
            }
        }
    }
}

// ===========================================================================
// attention middle (normalize, QK^T, softmax, PV). CTA = (win, head).
// Writes ctx as bf16 hi/lo for the proj GEMM.
// ===========================================================================
__global__ void __launch_bounds__(128)
attn2_kernel(const float* __restrict__ mask,
             const float* __restrict__ logit_scale)
{
    __shared__ float Q[64 * 36];
    __shared__ float K[64 * 36];
    __shared__ float VT[32 * 68];
    __shared__ float P[64 * 64];

    const int t = threadIdx.x, lane = t & 31, w = t >> 5;
    const int bid = blockIdx.x;
    const int win = bid >> 3, h = bid & 7;

    const size_t qb = (((size_t)0 * 2048 + win) * 8 + h) * 2048;
    const size_t kb = (((size_t)1 * 2048 + win) * 8 + h) * 2048;
    const size_t vb = (((size_t)2 * 2048 + win) * 8 + h) * 2048;

    for (int i = t; i < 512; i += 128) {
        float4 fq = *(const float4*)&g_qkv[qb + (size_t)i * 4];
        float4 fk = *(const float4*)&g_qkv[kb + (size_t)i * 4];
        float4 fv = *(const float4*)&g_qkv[vb + (size_t)i * 4];
        int tok = i >> 3, dg = (i & 7) * 4;
        *(float4*)&Q[tok * 36 + dg] = fq;
        *(float4*)&K[tok * 36 + dg] = fk;
        VT[(dg + 0) * 68 + tok] = fv.x;
        VT[(dg + 1) * 68 + tok] = fv.y;
        VT[(dg + 2) * 68 + tok] = fv.z;
        VT[(dg + 3) * 68 + tok] = fv.w;
    }
    __syncthreads();

    {
        int r = t & 63;
        float* Pm = (t < 64) ? Q : K;
        float s = 0.f;
#pragma unroll
        for (int dd = 0; dd < 32; dd += 4) {
            float4 v = *(const float4*)&Pm[r * 36 + dd];
            s += v.x * v.x + v.y * v.y + v.z * v.z + v.w * v.w;
        }
        float inv = rsqrtf(fmaxf(s, 1e-24f));
        if (t < 64) inv *= __expf(fminf(logit_scale[h], 4.605170185988092f));
#pragma unroll
        for (int dd = 0; dd < 32; dd += 4) {
            float4 v = *(const float4*)&Pm[r * 36 + dd];
            v.x *= inv; v.y *= inv; v.z *= inv; v.w *= inv;
            *(float4*)&Pm[r * 36 + dd] = v;
        }
    }
    __syncthreads();

    const float* rb = g_rel_bias + h * 4096;
    const float* mk = mask + (size_t)(win & 255) * 4096;
    for (int p4 = 0; p4 < 4; p4++) {
        int r0 = w * 16 + p4 * 4;
        unsigned long long a[4][2];
#pragma unroll
        for (int rr = 0; rr < 4; rr++) { a[rr][0] = 0ull; a[rr][1] = 0ull; }
#pragma unroll
        for (int dd = 0; dd < 32; dd += 4) {
            ulonglong2 k0 = *(const ulonglong2*)&K[lane * 36 + dd];
            ulonglong2 k1 = *(const ulonglong2*)&K[(lane + 32) * 36 + dd];
#pragma unroll
            for (int rr = 0; rr < 4; rr++) {
                ulonglong2 qv = *(const ulonglong2*)&Q[(r0 + rr) * 36 + dd];
                ffma2(a[rr][0], qv.x, k0.x); ffma2(a[rr][0], qv.y, k0.y);
                ffma2(a[rr][1], qv.x, k1.x); ffma2(a[rr][1], qv.y, k1.y);
            }
        }
#pragma unroll
        for (int rr = 0; rr < 4; rr++) {
            int r = r0 + rr, o = r * 64 + lane;
            float v0 = hsum2(a[rr][0]) + rb[o] + mk[o];
            float v1 = hsum2(a[rr][1]) + rb[o + 32] + mk[o + 32];
            float m = fmaxf(v0, v1);
#pragma unroll
            for (int off = 16; off; off >>= 1)
                m = fmaxf(m, __shfl_xor_sync(0xffffffffu, m, off));
            float e0 = __expf(v0 - m), e1 = __expf(v1 - m);
            float s = e0 + e1;
#pragma unroll
            for (int off = 16; off; off >>= 1)
                s += __shfl_xor_sync(0xffffffffu, s, off);
            float inv = 1.f / s;
            P[o] = e0 * inv;
            P[o + 32] = e1 * inv;
        }
    }
    __syncthreads();

    size_t cbase = ((size_t)win * 64) * 256 + h * 32 + lane;
    for (int p8 = 0; p8 < 2; p8++) {
        int r0 = w * 16 + p8 * 8;
        unsigned long long acc[8];
#pragma unroll
        for (int rr = 0; rr < 8; rr++) acc[rr] = 0ull;
#pragma unroll
        for (int j = 0; j < 64; j += 4) {
            ulonglong2 vv = *(const ulonglong2*)&VT[lane * 68 + j];
#pragma unroll
            for (int rr = 0; rr < 8; rr++) {
                ulonglong2 pp = *(const ulonglong2*)&P[(r0 + rr) * 64 + j];
                ffma2(acc[rr], pp.x, vv.x);
                ffma2(acc[rr], pp.y, vv.y);
            }
        }
#pragma unroll
        for (int rr = 0; rr < 8; rr++) {
            float o = hsum2(acc[rr]);
            __nv_bfloat16 hi, lo;
            bf_split(o, hi, lo);
            size_t idx = cbase + (size_t)(r0 + rr) * 256;
            g_chi[idx] = hi;
            g_clo[idx] = lo;
        }
    }
}

// ===========================================================================
extern "C" void kernel_launch(void* const* d_in, const int* in_sizes, int n_in,
                              void* d_out, int out_size)
{
    const float* x            = (const float*)d_in[0];
    const float* mask         = (const float*)d_in[1];
    const float* qkv_w        = (const float*)d_in[2];
    const float* q_bias       = (const float*)d_in[3];
    const float* v_bias       = (const float*)d_in[4];
    const float* logit_scale  = (const float*)d_in[5];
    const float* coords_table = (const float*)d_in[6];
    const float* mlp1_w       = (const float*)d_in[7];
    const float* mlp1_b       = (const float*)d_in[8];
    const float* mlp2_w       = (const float*)d_in[9];
    const float* proj_w       = (const float*)d_in[10];
    const float* proj_b       = (const float*)d_in[11];
    const int*   rel_pos_idx  = (const int*)d_in[12];
    float* out = (float*)d_out;

    cudaFuncSetAttribute(gemm_ar_kernel<6, 0>,
                         cudaFuncAttributeMaxDynamicSharedMemorySize, SMEM_GEMM);
    cudaFuncSetAttribute(gemm_ar_kernel<2, 1>,
                         cudaFuncAttributeMaxDynamicSharedMemorySize, SMEM_GEMM);

    prep_w_kernel<<<256, 256>>>(qkv_w, proj_w, q_bias, v_bias);
    cpb_kernel<<<1, 256>>>(coords_table, mlp1_w, mlp1_b, mlp2_w, rel_pos_idx);
    gemm_ar_kernel<6, 0><<<1024, 256, SMEM_GEMM>>>(x, nullptr, nullptr);
    attn2_kernel<<<2048 * 8, 128>>>(mask, logit_scale);
    gemm_ar_kernel<2, 1><<<1024, 256, SMEM_GEMM>>>(nullptr, proj_b, out);
}

// round 6
// speedup vs baseline: 1.1423x; 1.1423x over previous
#include <cuda_runtime.h>
#include <cuda_bf16.h>
#include <cstdint>
#include <math.h>

// ===========================================================================
// WindowAttentionV2: split-bf16 mma.sync everywhere (qkv gemm, attention,
// proj gemm). B=2048 win, N=64 tok, C=256, H=8, D=32.
// ===========================================================================

// ---- device scratch --------------------------------------------------------
__device__ float g_qkv[3u * 2048 * 8 * 2048];          // [(sec*2048+win)*8+h][tok*32+d]
__device__ __nv_bfloat16 g_xhi[131072u * 256];
__device__ __nv_bfloat16 g_xlo[131072u * 256];
__device__ __nv_bfloat16 g_chi[131072u * 256];
__device__ __nv_bfloat16 g_clo[131072u * 256];
__device__ __nv_bfloat16 g_wqkv_hi[768 * 256];         // [n][k]
__device__ __nv_bfloat16 g_wqkv_lo[768 * 256];
__device__ __nv_bfloat16 g_wproj_hi[256 * 256];
__device__ __nv_bfloat16 g_wproj_lo[256 * 256];
__device__ float g_rel_bias[8 * 64 * 64];
__device__ float g_bias_qkv[768];

// ---- helpers ----------------------------------------------------------------
__device__ __forceinline__ uint32_t smem_u32(const void* p) {
    uint32_t a;
    asm("{ .reg .u64 t; cvta.to.shared.u64 t, %1; cvt.u32.u64 %0, t; }"
        : "=r"(a) : "l"(p));
    return a;
}
__device__ __forceinline__ void mma_bf16(float* c, const uint32_t* a, const uint32_t* b) {
    asm volatile(
        "mma.sync.aligned.m16n8k16.row.col.f32.bf16.bf16.f32 "
        "{%0,%1,%2,%3}, {%4,%5,%6,%7}, {%8,%9}, {%0,%1,%2,%3};"
        : "+f"(c[0]), "+f"(c[1]), "+f"(c[2]), "+f"(c[3])
        : "r"(a[0]), "r"(a[1]), "r"(a[2]), "r"(a[3]), "r"(b[0]), "r"(b[1]));
}
__device__ __forceinline__ void ldm4(uint32_t* r, uint32_t addr) {
    asm volatile("ldmatrix.sync.aligned.m8n8.x4.shared.b16 {%0,%1,%2,%3}, [%4];"
                 : "=r"(r[0]), "=r"(r[1]), "=r"(r[2]), "=r"(r[3]) : "r"(addr));
}
__device__ __forceinline__ void cpasync16(uint32_t dst, const void* src) {
    asm volatile("cp.async.cg.shared.global [%0], [%1], 16;" :: "r"(dst), "l"(src));
}
__device__ __forceinline__ void bf_split(float v, __nv_bfloat16& hi, __nv_bfloat16& lo) {
    hi = __float2bfloat16(v);
    lo = __float2bfloat16(v - __bfloat162float(hi));
}
__device__ __forceinline__ uint32_t pack_bf(__nv_bfloat16 a, __nv_bfloat16 b) {
    return (uint32_t)__bfloat16_as_ushort(a) | ((uint32_t)__bfloat16_as_ushort(b) << 16);
}

// ===========================================================================
// prep_x: x fp32 -> bf16 hi/lo
// ===========================================================================
__global__ void prep_x_kernel(const float* __restrict__ x)
{
    int gid = blockIdx.x * blockDim.x + threadIdx.x;
    int gsz = gridDim.x * blockDim.x;
    for (int i = gid; i < 131072 * 64; i += gsz) {
        float4 f = ((const float4*)x)[i];
        __nv_bfloat16 h0, h1, h2, h3, l0, l1, l2, l3;
        bf_split(f.x, h0, l0); bf_split(f.y, h1, l1);
        bf_split(f.z, h2, l2); bf_split(f.w, h3, l3);
        ((__nv_bfloat162*)g_xhi)[2 * i]     = __nv_bfloat162(h0, h1);
        ((__nv_bfloat162*)g_xhi)[2 * i + 1] = __nv_bfloat162(h2, h3);
        ((__nv_bfloat162*)g_xlo)[2 * i]     = __nv_bfloat162(l0, l1);
        ((__nv_bfloat162*)g_xlo)[2 * i + 1] = __nv_bfloat162(l2, l3);
    }
}

// ===========================================================================
// prep_w: weights -> [n][k] bf16 hi/lo, qkv bias pack
// ===========================================================================
__global__ void prep_w_kernel(const float* __restrict__ qkv_w,
                              const float* __restrict__ proj_w,
                              const float* __restrict__ q_bias,
                              const float* __restrict__ v_bias)
{
    int gid = blockIdx.x * blockDim.x + threadIdx.x;
    int gsz = gridDim.x * blockDim.x;
    for (int i = gid; i < 768 * 256; i += gsz) {
        int n = i >> 8, k = i & 255;
        __nv_bfloat16 hi, lo;
        bf_split(qkv_w[(size_t)k * 768 + n], hi, lo);
        g_wqkv_hi[i] = hi; g_wqkv_lo[i] = lo;
    }
    for (int i = gid; i < 256 * 256; i += gsz) {
        int n = i >> 8, k = i & 255;
        __nv_bfloat16 hi, lo;
        bf_split(proj_w[(size_t)k * 256 + n], hi, lo);
        g_wproj_hi[i] = hi; g_wproj_lo[i] = lo;
    }
    for (int i = gid; i < 768; i += gsz)
        g_bias_qkv[i] = (i < 256) ? q_bias[i] : ((i < 512) ? 0.f : v_bias[i - 512]);
}

// ===========================================================================
// cpb: continuous position bias (window-independent)
// ===========================================================================
__global__ void cpb_kernel(const float* __restrict__ coords_table,
                           const float* __restrict__ mlp1_w,
                           const float* __restrict__ mlp1_b,
                           const float* __restrict__ mlp2_w,
                           const int*   __restrict__ rel_pos_index)
{
    __shared__ float bt[225 * 8];
    int t = threadIdx.x;
    if (t < 225) {
        float c0 = coords_table[t * 2 + 0];
        float c1 = coords_table[t * 2 + 1];
        float acc[8];
#pragma unroll
        for (int hh = 0; hh < 8; hh++) acc[hh] = 0.f;
        for (int k = 0; k < 512; k++) {
            float hv = fmaxf(c0 * mlp1_w[k] + c1 * mlp1_w[512 + k] + mlp1_b[k], 0.f);
#pragma unroll
            for (int hh = 0; hh < 8; hh++) acc[hh] += hv * mlp2_w[k * 8 + hh];
        }
#pragma unroll
        for (int hh = 0; hh < 8; hh++) bt[t * 8 + hh] = acc[hh];
    }
    __syncthreads();
    for (int idx = t; idx < 8 * 64 * 64; idx += blockDim.x) {
        int hh = idx >> 12;
        int ij = idx & 4095;
        float v = bt[rel_pos_index[ij] * 8 + hh];
        g_rel_bias[idx] = 16.f / (1.f + __expf(-v));
    }
}

// ===========================================================================
// gemm6: C[128,128] tile, split bf16, k32 double-buffered cp.async pipeline.
// MODE 0: A = x hi/lo, B = qkv w, epilogue scatter -> g_qkv (+bias)
// MODE 1: A = ctx hi/lo, B = proj w, epilogue -> Cout (+bias)
// Block: 256 thr = 8 warps (4m x 2n), warp tile 32x64. occ 2.
// ===========================================================================
#define LDC 40                        // chunk row stride (bf16)
#define CH_B  (128 * LDC * 2)         // 10240 B per matrix per polarity
#define BUF_B (4 * CH_B)              // AH AL BH BL = 40960
#define SMEM_G (2 * BUF_B)            // 81920

template<int MODE>
__global__ void __launch_bounds__(256, 2)
gemm6_kernel(const float* __restrict__ bias_ext, float* __restrict__ Cout)
{
    extern __shared__ __nv_bfloat16 smb[];
    const uint32_t sb = smem_u32(smb);

    const int t = threadIdx.x, lane = t & 31, w = t >> 5;
    const int wm = w & 3, wn = w >> 2;
    const int mtile = blockIdx.x, ntile = blockIdx.y;

    const __nv_bfloat16 *gAh, *gAl, *gBh, *gBl;
    if (MODE == 0) { gAh = g_xhi; gAl = g_xlo; gBh = g_wqkv_hi; gBl = g_wqkv_lo; }
    else           { gAh = g_chi; gAl = g_clo; gBh = g_wproj_hi; gBl = g_wproj_lo; }

    const size_t aoff = (size_t)mtile * 128 * 256;
    const size_t boff = (size_t)ntile * 128 * 256;

    auto stage = [&](int s, int buf) {
        const int k0 = s * 32;
        const uint32_t AH = sb + buf * BUF_B;
        const uint32_t AL = AH + CH_B;
        const uint32_t BH = AL + CH_B;
        const uint32_t BL = BH + CH_B;
#pragma unroll
        for (int rep = 0; rep < 2; rep++) {
            int idx = rep * 256 + t;           // 0..511
            int row = idx >> 2, cg = idx & 3;  // 4 x 16B per 32-col row
            uint32_t so = (uint32_t)(row * LDC + cg * 8) * 2;
            size_t go = (size_t)row * 256 + k0 + cg * 8;
            cpasync16(AH + so, gAh + aoff + go);
            cpasync16(AL + so, gAl + aoff + go);
            cpasync16(BH + so, gBh + boff + go);
            cpasync16(BL + so, gBl + boff + go);
        }
        asm volatile("cp.async.commit_group;" ::: "memory");
    };

    float acc[2][8][4];
#pragma unroll
    for (int mi = 0; mi < 2; mi++)
#pragma unroll
        for (int n8 = 0; n8 < 8; n8++)
#pragma unroll
            for (int r = 0; r < 4; r++) acc[mi][n8][r] = 0.f;

    stage(0, 0);
    stage(1, 1);

    for (int s = 0; s < 8; s++) {
        if (s < 7) asm volatile("cp.async.wait_group 1;" ::: "memory");
        else       asm volatile("cp.async.wait_group 0;" ::: "memory");
        __syncthreads();

        const uint32_t AH = sb + (s & 1) * BUF_B;
        const uint32_t AL = AH + CH_B;
        const uint32_t BH = AL + CH_B;
        const uint32_t BL = BH + CH_B;

#pragma unroll
        for (int ks = 0; ks < 2; ks++) {
            uint32_t ah[2][4], al[2][4];
            {
                int arow = wm * 32 + (lane & 15);
                int acol = ks * 16 + ((lane >> 4) << 3);
                uint32_t ao = (uint32_t)(arow * LDC + acol) * 2;
                ldm4(ah[0], AH + ao);
                ldm4(ah[1], AH + ao + 16 * LDC * 2);
                ldm4(al[0], AL + ao);
                ldm4(al[1], AL + ao + 16 * LDC * 2);
            }
            const int quad = lane >> 3, l8 = lane & 7;
            const int bcol = ks * 16 + ((quad & 1) << 3);
#pragma unroll
            for (int np = 0; np < 4; np++) {
                int brow = wn * 64 + np * 16 + ((quad >> 1) << 3) + l8;
                uint32_t bo = (uint32_t)(brow * LDC + bcol) * 2;
                uint32_t bq[4];
                ldm4(bq, BH + bo);
#pragma unroll
                for (int mi = 0; mi < 2; mi++) {
                    mma_bf16(acc[mi][2 * np + 0], ah[mi], bq + 0);   // hi*whi
                    mma_bf16(acc[mi][2 * np + 1], ah[mi], bq + 2);
                    mma_bf16(acc[mi][2 * np + 0], al[mi], bq + 0);   // lo*whi
                    mma_bf16(acc[mi][2 * np + 1], al[mi], bq + 2);
                }
                ldm4(bq, BL + bo);
#pragma unroll
                for (int mi = 0; mi < 2; mi++) {
                    mma_bf16(acc[mi][2 * np + 0], ah[mi], bq + 0);   // hi*wlo
                    mma_bf16(acc[mi][2 * np + 1], ah[mi], bq + 2);
                }
            }
        }
        __syncthreads();
        if (s + 2 < 8) stage(s + 2, s & 1);
    }

    // ---- epilogue -------------------------------------------------------------
    const int row_l = wm * 32 + (lane >> 2);
    const int col_l = wn * 64 + (lane & 3) * 2;
#pragma unroll
    for (int mi = 0; mi < 2; mi++) {
#pragma unroll
        for (int n8 = 0; n8 < 8; n8++) {
            int gc = ntile * 128 + col_l + n8 * 8;
            if (MODE == 0) {
                int sec = gc >> 8, hh = (gc >> 5) & 7, d = gc & 31;
                float b0 = g_bias_qkv[gc], b1 = g_bias_qkv[gc + 1];
#pragma unroll
                for (int half = 0; half < 2; half++) {
                    int row = mtile * 128 + row_l + mi * 16 + half * 8;
                    int win = row >> 6, tok = row & 63;
                    size_t addr = (((size_t)sec * 2048 + win) * 8 + hh) * 2048
                                  + (size_t)tok * 32 + d;
                    float2 v;
                    v.x = acc[mi][n8][2 * half + 0] + b0;
                    v.y = acc[mi][n8][2 * half + 1] + b1;
                    *(float2*)&g_qkv[addr] = v;
                }
            } else {
                float b0 = bias_ext[gc], b1 = bias_ext[gc + 1];
#pragma unroll
                for (int half = 0; half < 2; half++) {
                    int row = mtile * 128 + row_l + mi * 16 + half * 8;
                    float2 v;
                    v.x = acc[mi][n8][2 * half + 0] + b0;
                    v.y = acc[mi][n8][2 * half + 1] + b1;
                    *(float2*)&Cout[(size_t)row * 256 + gc] = v;
                }
            }
        }
    }
}

// ===========================================================================
// attn2: mma.sync attention middle. CTA = (win, head), 128 thr = 4 warps.
// Normalize fp32 -> QK^T (split bf16) -> softmax on frags -> PV (split bf16).
// Outputs ctx as bf16 hi/lo.
// ===========================================================================
#define LQ 40    // q/k hi/lo row stride (bf16)
#define LP 72    // P and VT row stride (bf16)

__global__ void __launch_bounds__(128)
attn2_kernel(const float* __restrict__ mask,
             const float* __restrict__ logit_scale)
{
    __shared__ char smraw[18432 + 4 * 5120 + 2 * 4608];   // 48128 B
    float* SQ = (float*)smraw;                  // [64][36] fp32 (dies after norm)
    float* SK = SQ + 64 * 36;
    __nv_bfloat16* PH = (__nv_bfloat16*)smraw;  // [64][72] (union with SQ/SK)
    __nv_bfloat16* PL = PH + 64 * LP;
    __nv_bfloat16* QH = (__nv_bfloat16*)(smraw + 18432);
    __nv_bfloat16* QL = QH + 64 * LQ;
    __nv_bfloat16* KH = QL + 64 * LQ;
    __nv_bfloat16* KL = KH + 64 * LQ;
    __nv_bfloat16* VTH = KL + 64 * LQ;          // [32][72]
    __nv_bfloat16* VTL = VTH + 32 * LP;

    const uint32_t uQH = smem_u32(QH), uQL = smem_u32(QL);
    const uint32_t uKH = smem_u32(KH), uKL = smem_u32(KL);
    const uint32_t uVH = smem_u32(VTH), uVL = smem_u32(VTL);
    const uint32_t uPH = smem_u32(PH), uPL = smem_u32(PL);

    const int t = threadIdx.x, lane = t & 31, w = t >> 5;
    const int win = blockIdx.x >> 3, h = blockIdx.x & 7;

    const float* qg = g_qkv + (((size_t)0 * 2048 + win) * 8 + h) * 2048;
    const float* kg = g_qkv + (((size_t)1 * 2048 + win) * 8 + h) * 2048;
    const float* vg = g_qkv + (((size_t)2 * 2048 + win) * 8 + h) * 2048;

    // ---- load q,k fp32 (staged), v -> VT hi/lo (transposed) -------------------
#pragma unroll
    for (int rep = 0; rep < 4; rep++) {
        int idx = rep * 128 + t;            // 0..511 float4
        int tok = idx >> 3, d4 = (idx & 7) * 4;
        float4 fq = *(const float4*)(qg + idx * 4);
        float4 fk = *(const float4*)(kg + idx * 4);
        float4 fv = *(const float4*)(vg + idx * 4);
        *(float4*)&SQ[tok * 36 + d4] = fq;
        *(float4*)&SK[tok * 36 + d4] = fk;
        float vv[4] = {fv.x, fv.y, fv.z, fv.w};
#pragma unroll
        for (int j = 0; j < 4; j++) {
            __nv_bfloat16 hi, lo;
            bf_split(vv[j], hi, lo);
            VTH[(d4 + j) * LP + tok] = hi;
            VTL[(d4 + j) * LP + tok] = lo;
        }
    }
    __syncthreads();

    // ---- normalize (t<64: q row t; t>=64: k row t-64), write hi/lo ------------
    {
        int r = t & 63;
        const float* src = (t < 64) ? (SQ + r * 36) : (SK + r * 36);
        __nv_bfloat16* dh = (t < 64) ? (QH + r * LQ) : (KH + r * LQ);
        __nv_bfloat16* dl = (t < 64) ? (QL + r * LQ) : (KL + r * LQ);
        float s = 0.f;
#pragma unroll
        for (int d = 0; d < 32; d += 4) {
            float4 v = *(const float4*)(src + d);
            s += v.x * v.x + v.y * v.y + v.z * v.z + v.w * v.w;
        }
        float inv = rsqrtf(fmaxf(s, 1e-24f));
        if (t < 64) inv *= __expf(fminf(logit_scale[h], 4.605170185988092f));
#pragma unroll
        for (int d = 0; d < 32; d += 2) {
            __nv_bfloat16 h0, l0, h1, l1;
            bf_split(src[d] * inv, h0, l0);
            bf_split(src[d + 1] * inv, h1, l1);
            *(uint32_t*)(dh + d) = pack_bf(h0, h1);
            *(uint32_t*)(dl + d) = pack_bf(l0, l1);
        }
    }
    __syncthreads();

    // ---- QK^T: m16 per warp, n=64, k=32, 3-term split --------------------------
    float acc[8][4];
#pragma unroll
    for (int n8 = 0; n8 < 8; n8++)
#pragma unroll
        for (int r = 0; r < 4; r++) acc[n8][r] = 0.f;

    const int quad = lane >> 3, l8 = lane & 7;
#pragma unroll
    for (int ks = 0; ks < 2; ks++) {
        uint32_t ah[4], al[4];
        {
            int arow = w * 16 + (lane & 15);
            int acol = ks * 16 + ((lane >> 4) << 3);
            uint32_t ao = (uint32_t)(arow * LQ + acol) * 2;
            ldm4(ah, uQH + ao);
            ldm4(al, uQL + ao);
        }
        const int bcol = ks * 16 + ((quad & 1) << 3);
#pragma unroll
        for (int np = 0; np < 4; np++) {
            int brow = np * 16 + ((quad >> 1) << 3) + l8;
            uint32_t bo = (uint32_t)(brow * LQ + bcol) * 2;
            uint32_t bq[4];
            ldm4(bq, uKH + bo);
            mma_bf16(acc[2 * np + 0], ah, bq + 0);
            mma_bf16(acc[2 * np + 1], ah, bq + 2);
            mma_bf16(acc[2 * np + 0], al, bq + 0);
            mma_bf16(acc[2 * np + 1], al, bq + 2);
            ldm4(bq, uKL + bo);
            mma_bf16(acc[2 * np + 0], ah, bq + 0);
            mma_bf16(acc[2 * np + 1], ah, bq + 2);
        }
    }

    // ---- + rel_bias + mask, softmax on fragments -------------------------------
    {
        const float* rb = g_rel_bias + h * 4096;
        const float* mk = mask + (size_t)(win & 255) * 4096;
        const int i0 = w * 16 + (lane >> 2);
        const int i1 = i0 + 8;
        const int jc = (lane & 3) * 2;
#pragma unroll
        for (int n8 = 0; n8 < 8; n8++) {
            int o0 = i0 * 64 + n8 * 8 + jc;
            int o1 = i1 * 64 + n8 * 8 + jc;
            float2 r0 = *(const float2*)(rb + o0), m0 = *(const float2*)(mk + o0);
            float2 r1 = *(const float2*)(rb + o1), m1 = *(const float2*)(mk + o1);
            acc[n8][0] += r0.x + m0.x;  acc[n8][1] += r0.y + m0.y;
            acc[n8][2] += r1.x + m1.x;  acc[n8][3] += r1.y + m1.y;
        }
        float mx0 = -1e30f, mx1 = -1e30f;
#pragma unroll
        for (int n8 = 0; n8 < 8; n8++) {
            mx0 = fmaxf(mx0, fmaxf(acc[n8][0], acc[n8][1]));
            mx1 = fmaxf(mx1, fmaxf(acc[n8][2], acc[n8][3]));
        }
        mx0 = fmaxf(mx0, __shfl_xor_sync(0xffffffffu, mx0, 1));
        mx0 = fmaxf(mx0, __shfl_xor_sync(0xffffffffu, mx0, 2));
        mx1 = fmaxf(mx1, __shfl_xor_sync(0xffffffffu, mx1, 1));
        mx1 = fmaxf(mx1, __shfl_xor_sync(0xffffffffu, mx1, 2));
        float s0 = 0.f, s1 = 0.f;
#pragma unroll
        for (int n8 = 0; n8 < 8; n8++) {
            acc[n8][0] = __expf(acc[n8][0] - mx0);
            acc[n8][1] = __expf(acc[n8][1] - mx0);
            acc[n8][2] = __expf(acc[n8][2] - mx1);
            acc[n8][3] = __expf(acc[n8][3] - mx1);
            s0 += acc[n8][0] + acc[n8][1];
            s1 += acc[n8][2] + acc[n8][3];
        }
        s0 += __shfl_xor_sync(0xffffffffu, s0, 1);
        s0 += __shfl_xor_sync(0xffffffffu, s0, 2);
        s1 += __shfl_xor_sync(0xffffffffu, s1, 1);
        s1 += __shfl_xor_sync(0xffffffffu, s1, 2);
        float inv0 = 1.f / s0, inv1 = 1.f / s1;
#pragma unroll
        for (int n8 = 0; n8 < 8; n8++) {
            int c0 = n8 * 8 + jc;
            float p00 = acc[n8][0] * inv0, p01 = acc[n8][1] * inv0;
            float p10 = acc[n8][2] * inv1, p11 = acc[n8][3] * inv1;
            __nv_bfloat16 h0, l0, h1, l1;
            bf_split(p00, h0, l0); bf_split(p01, h1, l1);
            *(uint32_t*)(PH + i0 * LP + c0) = pack_bf(h0, h1);
            *(uint32_t*)(PL + i0 * LP + c0) = pack_bf(l0, l1);
            bf_split(p10, h0, l0); bf_split(p11, h1, l1);
            *(uint32_t*)(PH + i1 * LP + c0) = pack_bf(h0, h1);
            *(uint32_t*)(PL + i1 * LP + c0) = pack_bf(l0, l1);
        }
    }
    __syncwarp();

    // ---- PV: m16 per warp, n=32, k=64, 3-term split -----------------------------
    float acc2[4][4];
#pragma unroll
    for (int n8 = 0; n8 < 4; n8++)
#pragma unroll
        for (int r = 0; r < 4; r++) acc2[n8][r] = 0.f;

#pragma unroll
    for (int ks = 0; ks < 4; ks++) {
        uint32_t ph[4], pl[4];
        {
            int arow = w * 16 + (lane & 15);
            int acol = ks * 16 + ((lane >> 4) << 3);
            uint32_t ao = (uint32_t)(arow * LP + acol) * 2;
            ldm4(ph, uPH + ao);
            ldm4(pl, uPL + ao);
        }
        const int bcol = ks * 16 + ((quad & 1) << 3);
#pragma unroll
        for (int np = 0; np < 2; np++) {
            int brow = np * 16 + ((quad >> 1) << 3) + l8;
            uint32_t bo = (uint32_t)(brow * LP + bcol) * 2;
            uint32_t bq[4];
            ldm4(bq, uVH + bo);
            mma_bf16(acc2[2 * np + 0], ph, bq + 0);
            mma_bf16(acc2[2 * np + 1], ph, bq + 2);
            mma_bf16(acc2[2 * np + 0], pl, bq + 0);
            mma_bf16(acc2[2 * np + 1], pl, bq + 2);
            ldm4(bq, uVL + bo);
            mma_bf16(acc2[2 * np + 0], ph, bq + 0);
            mma_bf16(acc2[2 * np + 1], ph, bq + 2);
        }
    }

    // ---- store ctx as bf16 hi/lo -------------------------------------------------
    {
        const int i0 = w * 16 + (lane >> 2);
        const int i1 = i0 + 8;
        const int dc = (lane & 3) * 2;
        size_t b0 = ((size_t)win * 64 + i0) * 256 + h * 32;
        size_t b1 = ((size_t)win * 64 + i1) * 256 + h * 32;
#pragma unroll
        for (int n8 = 0; n8 < 4; n8++) {
            int d = n8 * 8 + dc;
            __nv_bfloat16 h0, l0, h1, l1;
            bf_split(acc2[n8][0], h0, l0); bf_split(acc2[n8][1], h1, l1);
            *(uint32_t*)(g_chi + b0 + d) = pack_bf(h0, h1);
            *(uint32_t*)(g_clo + b0 + d) = pack_bf(l0, l1);
            bf_split(acc2[n8][2], h0, l0); bf_split(acc2[n8][3], h1, l1);
            *(uint32_t*)(g_chi + b1 + d) = pack_bf(h0, h1);
            *(uint32_t*)(g_clo + b1 + d) = pack_bf(l0, l1);
        }
    }
}

// ===========================================================================
extern "C" void kernel_launch(void* const* d_in, const int* in_sizes, int n_in,
                              void* d_out, int out_size)
{
    const float* x            = (const float*)d_in[0];
    const float* mask         = (const float*)d_in[1];
    const float* qkv_w        = (const float*)d_in[2];
    const float* q_bias       = (const float*)d_in[3];
    const float* v_bias       = (const float*)d_in[4];
    const float* logit_scale  = (const float*)d_in[5];
    const float* coords_table = (const float*)d_in[6];
    const float* mlp1_w       = (const float*)d_in[7];
    const float* mlp1_b       = (const float*)d_in[8];
    const float* mlp2_w       = (const float*)d_in[9];
    const float* proj_w       = (const float*)d_in[10];
    const float* proj_b       = (const float*)d_in[11];
    const int*   rel_pos_idx  = (const int*)d_in[12];
    float* out = (float*)d_out;

    cudaFuncSetAttribute(gemm6_kernel<0>,
                         cudaFuncAttributeMaxDynamicSharedMemorySize, SMEM_G);
    cudaFuncSetAttribute(gemm6_kernel<1>,
                         cudaFuncAttributeMaxDynamicSharedMemorySize, SMEM_G);

    prep_x_kernel<<<4096, 256>>>(x);
    prep_w_kernel<<<256, 256>>>(qkv_w, proj_w, q_bias, v_bias);
    cpb_kernel<<<1, 256>>>(coords_table, mlp1_w, mlp1_b, mlp2_w, rel_pos_idx);
    gemm6_kernel<0><<<dim3(1024, 6), 256, SMEM_G>>>(nullptr, nullptr);
    attn2_kernel<<<2048 * 8, 128>>>(mask, logit_scale);
    gemm6_kernel<1><<<dim3(1024, 2), 256, SMEM_G>>>(proj_b, out);
}